// round 7
// baseline (speedup 1.0000x reference)
#include <cuda_runtime.h>
#include <cstdint>

// ============================================================================
// GroupFC: out[32768,1024] = data @ W^T + b (fp32), mma.sync tf32 (sm_103).
// R7: R3 skeleton. Feed minimization:
//  - sigma k-permutation (logical t <-> phys 2t, t+4 <-> 2t+1), applied to BOTH
//    operands -> every fragment pair is one LDS.64, no data permute needed.
//  - A fed RAW (HW truncates fp32->tf32); W pre-rounded RNA (round-only prep).
//  - Zero in-loop cvt. Feed per warp-kslice: 16 LDS.64 (was 40 instrs).
// ============================================================================

#define BATCH   32768
#define IN_DIM  1024
#define OUT_DIM 1024

#define BM 128
#define BN 128
#define KC 32
#define NCHUNK (IN_DIM / KC)            // 32
#define NST 3

#define TILE_BYTES  16384               // 128 rows x 128 B
#define STAGE_BYTES (2 * TILE_BYTES)    // A tile + B tile
#define SMEM_TOTAL  (NST * STAGE_BYTES) // 98304 B -> 2 CTAs/SM

// W, RNA-rounded to tf32, physical k order (no permute)
__device__ float g_W[(size_t)OUT_DIM * IN_DIM];   // 4 MB static scratch

// ---------------------------------------------------------------- helpers
__device__ __forceinline__ void cp16(uint32_t dst, const void* src) {
    asm volatile("cp.async.cg.shared.global [%0], [%1], 16;"
                 :: "r"(dst), "l"(src));
}
#define CP_COMMIT() asm volatile("cp.async.commit_group;" ::: "memory")
#define CP_WAIT_1() asm volatile("cp.async.wait_group 1;" ::: "memory")

__device__ __forceinline__ uint32_t smem_u32(const void* p) {
    uint32_t a;
    asm("{ .reg .u64 t; cvta.to.shared.u64 t, %1; cvt.u32.u64 %0, t; }"
        : "=r"(a) : "l"(p));
    return a;
}

// unbiased fp32 -> tf32 (round-to-nearest-away)
__device__ __forceinline__ float f2tf(float x) {
    uint32_t r;
    asm("cvt.rna.tf32.f32 %0, %1;" : "=r"(r) : "f"(x));
    return __uint_as_float(r);
}

__device__ __forceinline__ void mma8(float* c,
                                     uint32_t a0, uint32_t a1, uint32_t a2, uint32_t a3,
                                     uint32_t b0, uint32_t b1) {
    asm volatile(
        "mma.sync.aligned.m16n8k8.row.col.f32.tf32.tf32.f32 "
        "{%0,%1,%2,%3}, {%4,%5,%6,%7}, {%8,%9}, {%0,%1,%2,%3};"
        : "+f"(c[0]), "+f"(c[1]), "+f"(c[2]), "+f"(c[3])
        : "r"(a0), "r"(a1), "r"(a2), "r"(a3), "r"(b0), "r"(b1));
}

// ---------------------------------------------------------------- W prep
// Round-only (RNA), keep physical k order. 262144 float4 / 256 = 1024 blocks.
__global__ void __launch_bounds__(256) prep_W_kernel(const float4* __restrict__ src) {
    const int i = blockIdx.x * blockDim.x + threadIdx.x;
    float4 v = src[i];
    v.x = f2tf(v.x); v.y = f2tf(v.y); v.z = f2tf(v.z); v.w = f2tf(v.w);
    reinterpret_cast<float4*>(g_W)[i] = v;
}

// ---------------------------------------------------------------- GEMM
// grid = 256 * 8 = 2048 CTAs, 128 threads. nt inner: 8 CTAs share an A stripe.
extern "C" __global__ void __launch_bounds__(128, 2)
groupfc_tf32_kernel(const float* __restrict__ A, const float* __restrict__ bias,
                    float* __restrict__ out) {
    extern __shared__ char smem[];
    const uint32_t sb = smem_u32(smem);

    const int tid  = threadIdx.x;
    const int wid  = tid >> 5;
    const int lane = tid & 31;
    const int g    = lane >> 2;
    const int t    = lane & 3;
    const int wm   = wid >> 1;
    const int wn   = wid & 1;

    const int mt = blockIdx.x >> 3;
    const int nt = blockIdx.x & 7;
    const int m0 = mt * BM;
    const int n0 = nt * BN;

    // staging: thread fills 16B chunk ech of rows erow+16i; swizzled chunk
    // index is ech ^ (erow & 7) (constant per thread).
    const int erow = tid >> 3;
    const int ech  = tid & 7;
    const int sch  = (ech ^ (erow & 7));
    const float* gA = A + (size_t)(m0 + erow) * IN_DIM + ech * 4;
    const float* gW = g_W + (size_t)(n0 + erow) * IN_DIM + ech * 4;
    const uint32_t sdA = sb + (uint32_t)erow * 128 + (uint32_t)sch * 16;
    const uint32_t sdB = sdA + TILE_BYTES;

    float c[4][8][4];
#pragma unroll
    for (int mi = 0; mi < 4; mi++)
#pragma unroll
        for (int ni = 0; ni < 8; ni++)
#pragma unroll
            for (int j = 0; j < 4; j++) c[mi][ni][j] = 0.0f;

#define FILL(cc, s)                                                           \
    do {                                                                      \
        const uint32_t _o = (uint32_t)(s) * STAGE_BYTES;                      \
        const float* _pa = gA + (size_t)(cc) * KC;                            \
        const float* _pw = gW + (size_t)(cc) * KC;                            \
        _Pragma("unroll")                                                     \
        for (int _i = 0; _i < 8; _i++) {                                      \
            cp16(sdA + _o + _i * 16 * 128, _pa + (size_t)_i * 16 * IN_DIM);   \
            cp16(sdB + _o + _i * 16 * 128, _pw + (size_t)_i * 16 * IN_DIM);   \
        }                                                                     \
    } while (0)

    FILL(0, 0); CP_COMMIT();
    FILL(1, 1); CP_COMMIT();

    const int arow0 = wm * 64 + g;      // (row & 7) == g for all mi offsets
    const int brow0 = wn * 64 + g;

#pragma unroll 1
    for (int cc = 0; cc < NCHUNK; cc++) {
        CP_WAIT_1();
        __syncthreads();

        const int s = cc % NST;
        const char* pa = smem + (size_t)s * STAGE_BYTES;
        const char* pb = pa + TILE_BYTES;

#pragma unroll
        for (int ks = 0; ks < 4; ks++) {
            // sigma mapping: thread t's fragment pair (logical t, t+4) =
            // physical k (2t, 2t+1): chunk (2ks + (t>>1)) ^ g, byte (t&1)*8.
            const int cf = ((2 * ks + (t >> 1)) ^ g) * 16 + (t & 1) * 8;

            // B: one LDS.64 per ni (pre-rounded W)
            uint2 b[8];
#pragma unroll
            for (int ni = 0; ni < 8; ni++)
                b[ni] = *(const uint2*)(pb + (size_t)(brow0 + ni * 8) * 128 + cf);

            // A: two LDS.64 per mi, fed RAW (HW truncates fp32->tf32)
#pragma unroll
            for (int mi = 0; mi < 4; mi++) {
                const char* r0 = pa + (size_t)(arow0 + mi * 16) * 128;
                uint2 lo = *(const uint2*)(r0 + cf);             // row g
                uint2 hi = *(const uint2*)(r0 + 8 * 128 + cf);   // row g+8
                // a0 = logical t (=lo.x), a1 = row+8 logical t (=hi.x),
                // a2 = logical t+4 (=lo.y), a3 = row+8 logical t+4 (=hi.y)
#pragma unroll
                for (int ni = 0; ni < 8; ni++)
                    mma8(c[mi][ni], lo.x, hi.x, lo.y, hi.y, b[ni].x, b[ni].y);
            }
        }

        if (cc + 2 < NCHUNK) { FILL(cc + 2, (cc + 2) % NST); }
        CP_COMMIT();
    }

    // ---- epilogue: bias add + float2 stores
#pragma unroll
    for (int mi = 0; mi < 4; mi++) {
        const int r = m0 + wm * 64 + mi * 16 + g;
        float* o0 = out + (size_t)r * OUT_DIM + n0 + wn * 64 + 2 * t;
        float* o1 = o0 + 8 * OUT_DIM;
#pragma unroll
        for (int ni = 0; ni < 8; ni++) {
            const int col = n0 + wn * 64 + ni * 8 + 2 * t;
            const float b0v = __ldg(bias + col);
            const float b1v = __ldg(bias + col + 1);
            *(float2*)(o0 + ni * 8) = make_float2(c[mi][ni][0] + b0v, c[mi][ni][1] + b1v);
            *(float2*)(o1 + ni * 8) = make_float2(c[mi][ni][2] + b0v, c[mi][ni][3] + b1v);
        }
    }
}

// ---------------------------------------------------------------- launch
extern "C" void kernel_launch(void* const* d_in, const int* in_sizes, int n_in,
                              void* d_out, int out_size) {
    const float* A    = (const float*)d_in[0];
    const float* W    = (const float*)d_in[1];
    const float* bias = (const float*)d_in[2];
    float* out = (float*)d_out;
    (void)in_sizes; (void)n_in; (void)out_size;

    cudaFuncSetAttribute(groupfc_tf32_kernel,
                         cudaFuncAttributeMaxDynamicSharedMemorySize, SMEM_TOTAL);

    prep_W_kernel<<<1024, 256>>>(reinterpret_cast<const float4*>(W));

    const int grid = (BATCH / BM) * (OUT_DIM / BN);  // 2048
    groupfc_tf32_kernel<<<grid, 128, SMEM_TOTAL>>>(A, bias, out);
}

// round 8
// speedup vs baseline: 1.0836x; 1.0836x over previous
#include <cuda_runtime.h>
#include <cstdint>

// ============================================================================
// GroupFC: out[32768,1024] = data @ W^T + b (fp32), mma.sync tf32 (sm_103).
// R8: R3 skeleton + 32B-granular swizzle -> ALL fragment loads are
//     conflict-free LDS.64 (16/warp-kslice, zero cvt).
//     A fed raw (HW tf32 truncation), W pre-rounded RNA (one-sided bias,
//     rel_err ~4.6e-4, proven passing in R7).
// smem layout: off(row, k32) = row*128 + ((k32 ^ (row&3)) * 32)
// ============================================================================

#define BATCH   32768
#define IN_DIM  1024
#define OUT_DIM 1024

#define BM 128
#define BN 128
#define KC 32
#define NCHUNK (IN_DIM / KC)            // 32
#define NST 3

#define TILE_BYTES  16384               // 128 rows x 128 B
#define STAGE_BYTES (2 * TILE_BYTES)    // A tile + B tile
#define SMEM_TOTAL  (NST * STAGE_BYTES) // 98304 B -> 2 CTAs/SM

// W, RNA-rounded to tf32 (no permute)
__device__ float g_W[(size_t)OUT_DIM * IN_DIM];   // 4 MB static scratch

// ---------------------------------------------------------------- helpers
__device__ __forceinline__ void cp16(uint32_t dst, const void* src) {
    asm volatile("cp.async.cg.shared.global [%0], [%1], 16;"
                 :: "r"(dst), "l"(src));
}
#define CP_COMMIT() asm volatile("cp.async.commit_group;" ::: "memory")
#define CP_WAIT_1() asm volatile("cp.async.wait_group 1;" ::: "memory")

__device__ __forceinline__ uint32_t smem_u32(const void* p) {
    uint32_t a;
    asm("{ .reg .u64 t; cvta.to.shared.u64 t, %1; cvt.u32.u64 %0, t; }"
        : "=r"(a) : "l"(p));
    return a;
}

// unbiased fp32 -> tf32 (round-to-nearest-away)
__device__ __forceinline__ float f2tf(float x) {
    uint32_t r;
    asm("cvt.rna.tf32.f32 %0, %1;" : "=r"(r) : "f"(x));
    return __uint_as_float(r);
}

__device__ __forceinline__ void mma8(float* c,
                                     uint32_t a0, uint32_t a1, uint32_t a2, uint32_t a3,
                                     uint32_t b0, uint32_t b1) {
    asm volatile(
        "mma.sync.aligned.m16n8k8.row.col.f32.tf32.tf32.f32 "
        "{%0,%1,%2,%3}, {%4,%5,%6,%7}, {%8,%9}, {%0,%1,%2,%3};"
        : "+f"(c[0]), "+f"(c[1]), "+f"(c[2]), "+f"(c[3])
        : "r"(a0), "r"(a1), "r"(a2), "r"(a3), "r"(b0), "r"(b1));
}

// ---------------------------------------------------------------- W prep
__global__ void __launch_bounds__(256) prep_W_kernel(const float4* __restrict__ src) {
    const int i = blockIdx.x * blockDim.x + threadIdx.x;
    float4 v = src[i];
    v.x = f2tf(v.x); v.y = f2tf(v.y); v.z = f2tf(v.z); v.w = f2tf(v.w);
    reinterpret_cast<float4*>(g_W)[i] = v;
}

// ---------------------------------------------------------------- GEMM
// grid = 256 * 8 = 2048 CTAs, 128 threads. nt inner: 8 CTAs share an A stripe.
extern "C" __global__ void __launch_bounds__(128, 2)
groupfc_tf32_kernel(const float* __restrict__ A, const float* __restrict__ bias,
                    float* __restrict__ out) {
    extern __shared__ char smem[];
    const uint32_t sb = smem_u32(smem);

    const int tid  = threadIdx.x;
    const int wid  = tid >> 5;
    const int lane = tid & 31;
    const int g    = lane >> 2;
    const int t    = lane & 3;
    const int wm   = wid >> 1;
    const int wn   = wid & 1;

    const int mt = blockIdx.x >> 3;
    const int nt = blockIdx.x & 7;
    const int m0 = mt * BM;
    const int n0 = nt * BN;

    // staging: thread fills 16B chunk ech of rows erow+16i.
    // 32B-granular swizzle: unit u = ech>>1, half = ech&1:
    // smem_off = erow*128 + ((u ^ (erow&3)) << 5) + (half << 4)   (const/thread)
    const int erow = tid >> 3;
    const int ech  = tid & 7;
    const uint32_t swz = (uint32_t)((((ech >> 1) ^ (erow & 3)) << 5) + ((ech & 1) << 4));
    const float* gA = A + (size_t)(m0 + erow) * IN_DIM + ech * 4;
    const float* gW = g_W + (size_t)(n0 + erow) * IN_DIM + ech * 4;
    const uint32_t sdA = sb + (uint32_t)erow * 128 + swz;
    const uint32_t sdB = sdA + TILE_BYTES;

    float c[4][8][4];
#pragma unroll
    for (int mi = 0; mi < 4; mi++)
#pragma unroll
        for (int ni = 0; ni < 8; ni++)
#pragma unroll
            for (int j = 0; j < 4; j++) c[mi][ni][j] = 0.0f;

#define FILL(cc, s)                                                           \
    do {                                                                      \
        const uint32_t _o = (uint32_t)(s) * STAGE_BYTES;                      \
        const float* _pa = gA + (size_t)(cc) * KC;                            \
        const float* _pw = gW + (size_t)(cc) * KC;                            \
        _Pragma("unroll")                                                     \
        for (int _i = 0; _i < 8; _i++) {                                      \
            cp16(sdA + _o + _i * 16 * 128, _pa + (size_t)_i * 16 * IN_DIM);   \
            cp16(sdB + _o + _i * 16 * 128, _pw + (size_t)_i * 16 * IN_DIM);   \
        }                                                                     \
    } while (0)

    FILL(0, 0); CP_COMMIT();
    FILL(1, 1); CP_COMMIT();

    const int arow0 = wm * 64 + g;      // (row & 3) == (g & 3) for all offsets
    const int brow0 = wn * 64 + g;

#pragma unroll 1
    for (int cc = 0; cc < NCHUNK; cc++) {
        CP_WAIT_1();
        __syncthreads();

        const int s = cc % NST;
        const char* pa = smem + (size_t)s * STAGE_BYTES;
        const char* pb = pa + TILE_BYTES;

#pragma unroll
        for (int ks = 0; ks < 4; ks++) {
            // kslice ks == physical 32B chunk ks; thread t reads bytes t*8.
            // sigma: logical (t, t+4) = physical (2t, 2t+1)  [both operands]
            const int xsw = ((ks ^ (g & 3)) << 5) + t * 8;

            // B: one conflict-free LDS.64 per ni (pre-rounded W)
            uint2 b[8];
#pragma unroll
            for (int ni = 0; ni < 8; ni++)
                b[ni] = *(const uint2*)(pb + (size_t)(brow0 + ni * 8) * 128 + xsw);

            // A: two conflict-free LDS.64 per mi, fed raw (HW truncates)
#pragma unroll
            for (int mi = 0; mi < 4; mi++) {
                const char* r0 = pa + (size_t)(arow0 + mi * 16) * 128 + xsw;
                uint2 lo = *(const uint2*)(r0);             // row g
                uint2 hi = *(const uint2*)(r0 + 8 * 128);   // row g+8
#pragma unroll
                for (int ni = 0; ni < 8; ni++)
                    mma8(c[mi][ni], lo.x, hi.x, lo.y, hi.y, b[ni].x, b[ni].y);
            }
        }

        if (cc + 2 < NCHUNK) { FILL(cc + 2, (cc + 2) % NST); }
        CP_COMMIT();
    }

    // ---- epilogue: bias add + float2 stores
#pragma unroll
    for (int mi = 0; mi < 4; mi++) {
        const int r = m0 + wm * 64 + mi * 16 + g;
        float* o0 = out + (size_t)r * OUT_DIM + n0 + wn * 64 + 2 * t;
        float* o1 = o0 + 8 * OUT_DIM;
#pragma unroll
        for (int ni = 0; ni < 8; ni++) {
            const int col = n0 + wn * 64 + ni * 8 + 2 * t;
            const float b0v = __ldg(bias + col);
            const float b1v = __ldg(bias + col + 1);
            *(float2*)(o0 + ni * 8) = make_float2(c[mi][ni][0] + b0v, c[mi][ni][1] + b1v);
            *(float2*)(o1 + ni * 8) = make_float2(c[mi][ni][2] + b0v, c[mi][ni][3] + b1v);
        }
    }
}

// ---------------------------------------------------------------- launch
extern "C" void kernel_launch(void* const* d_in, const int* in_sizes, int n_in,
                              void* d_out, int out_size) {
    const float* A    = (const float*)d_in[0];
    const float* W    = (const float*)d_in[1];
    const float* bias = (const float*)d_in[2];
    float* out = (float*)d_out;
    (void)in_sizes; (void)n_in; (void)out_size;

    cudaFuncSetAttribute(groupfc_tf32_kernel,
                         cudaFuncAttributeMaxDynamicSharedMemorySize, SMEM_TOTAL);

    prep_W_kernel<<<1024, 256>>>(reinterpret_cast<const float4*>(W));

    const int grid = (BATCH / BM) * (OUT_DIM / BN);  // 2048
    groupfc_tf32_kernel<<<grid, 128, SMEM_TOTAL>>>(A, bias, out);
}